// round 5
// baseline (speedup 1.0000x reference)
#include <cuda_runtime.h>
#include <cuda_fp16.h>
#include <cstdint>

#define NSEQ 16384

__device__ __half g_Wh[4096 * 64];   // [ki][j] fp16 W
__device__ float  g_bias[4096];      // [ki]

// smem byte offsets
#define SM_W     0                    // [128 n][64 j] fp16 swizzled  (16384)
#define SM_BIAS  16384                // 128 f32                       (512)
#define SM_X     16896                // 2 buffers x 16384 (fp16 X, swizzled)
#define SM_XBUF  16384
#define SM_TOTAL (16896 + 2 * 16384)  // 49664

__device__ __forceinline__ uint32_t smem_u32(const void *p) {
    uint32_t a;
    asm("{ .reg .u64 t; cvta.to.shared.u64 t, %1; cvt.u32.u64 %0, t; }" : "=r"(a) : "l"(p));
    return a;
}
__device__ __forceinline__ void ldsm4(uint32_t *r, uint32_t a) {
    asm volatile("ldmatrix.sync.aligned.m8n8.x4.shared.b16 {%0,%1,%2,%3}, [%4];"
                 : "=r"(r[0]), "=r"(r[1]), "=r"(r[2]), "=r"(r[3]) : "r"(a));
}
__device__ __forceinline__ void mma16816(float *c, const uint32_t *a, uint32_t b0, uint32_t b1) {
    asm volatile("mma.sync.aligned.m16n8k16.row.col.f32.f16.f16.f32 "
                 "{%0,%1,%2,%3}, {%4,%5,%6,%7}, {%8,%9}, {%0,%1,%2,%3};"
                 : "+f"(c[0]), "+f"(c[1]), "+f"(c[2]), "+f"(c[3])
                 : "r"(a[0]), "r"(a[1]), "r"(a[2]), "r"(a[3]), "r"(b0), "r"(b1));
}

// ---------------------------------------------------------------------------
// Prep: W -> fp16 g_Wh [ki][j]; bias[ki] = cm[k] . Wcm[k][i]
// ---------------------------------------------------------------------------
__global__ void prep_kernel(const float *__restrict__ W, const float *__restrict__ cm) {
    const int k = blockIdx.x, tid = threadIdx.x;
    const float *Wk = W + k * 64 * 128;
#pragma unroll
    for (int t = 0; t < 16; ++t) {
        int e = tid + t * 256;            // (i, j)
        int i = e >> 6, j = e & 63;
        g_Wh[(k * 64 + i) * 64 + j] = __float2half_rn(Wk[i * 128 + j]);
    }
    if (tid < 64) {
        const int i = tid;
        const float *cmk = cm + k * 64;
        float s = 0.f;
#pragma unroll 8
        for (int j = 0; j < 64; ++j)
            s = fmaf(cmk[j], Wk[i * 128 + 64 + j], s);
        g_bias[k * 64 + i] = s;
    }
}

// ---------------------------------------------------------------------------
// Main: 512 threads, CTA tile 128m x 128n, K=64, 8 m-tiles per CTA.
// 16 warps as 8m x 2n (warp = 16m x 64n = one full i-group).
// Single-pass fp16. B (W tile) fragments loaded ONCE into 64 regs/warp ->
// mainloop is 4 ldsm4(A) + 32 HMMA per tile. X double-buffered; LDG(t+1)
// overlaps mma(t). Epilogue: clip + 2-shfl L1-normalize + direct STG.64.
// ---------------------------------------------------------------------------
__global__ __launch_bounds__(512, 1)
void mma_kernel(const float *__restrict__ x, float *__restrict__ out) {
    extern __shared__ char smem[];
    const uint32_t sb = smem_u32(smem);
    const int tid = threadIdx.x;
    const int lane = tid & 31, wid = tid >> 5;
    const int wm = wid & 7, wn = wid >> 3;
    const int ki0 = blockIdx.x * 128;
    const int grp = blockIdx.y;

    // ---- stage W (swizzled) + bias ----
    {
        const int n = tid & 127, c2 = tid >> 7;
        const uint4 *wsrc = reinterpret_cast<const uint4 *>(g_Wh + (ki0 + n) * 64);
        const int n7 = n & 7;
#pragma unroll
        for (int q = 0; q < 2; ++q) {
            const int ch = c2 * 2 + q;
            *reinterpret_cast<uint4 *>(smem + SM_W + n * 128 + (ch ^ n7) * 16) = wsrc[ch];
        }
        if (tid < 128) reinterpret_cast<float *>(smem + SM_BIAS)[tid] = g_bias[ki0 + tid];
    }

    const int mm = tid & 127, jh = tid >> 7, mm7 = mm & 7;

    auto ldx = [&](int t, float *xf) {
        const int m0 = (grp * 8 + t) * 128;
        const float *xb = x + ((size_t)(m0 >> 14)) * (64 * (size_t)NSEQ) + (m0 & (NSEQ - 1)) + mm;
#pragma unroll
        for (int e = 0; e < 16; ++e)
            xf[e] = xb[(size_t)(jh * 16 + e) * NSEQ];
    };
    auto stx = [&](int b, const float *xf) {
        char *base = smem + SM_X + b * SM_XBUF + mm * 128;
#pragma unroll
        for (int q = 0; q < 2; ++q) {
            uint32_t hp[4];
#pragma unroll
            for (int e = 0; e < 4; ++e) {
                const __half h0 = __float2half_rn(xf[q * 8 + 2 * e]);
                const __half h1 = __float2half_rn(xf[q * 8 + 2 * e + 1]);
                hp[e] = (uint32_t)__half_as_ushort(h0) | ((uint32_t)__half_as_ushort(h1) << 16);
            }
            *reinterpret_cast<uint4 *>(base + ((jh * 2 + q) ^ mm7) * 16) =
                make_uint4(hp[0], hp[1], hp[2], hp[3]);
        }
    };

    // lane-constant ldmatrix addressing
    const uint32_t aA0 = sb + SM_X + (uint32_t)(wm * 16 + (lane & 15)) * 128;
    const int selA = lane >> 4;
    const int rBl = (lane & 7) + ((lane >> 4) << 3);
    const uint32_t aB0 = sb + SM_W + (uint32_t)(wn * 64 + rBl) * 128;
    const int selB = (lane >> 3) & 1;
    const int l7 = lane & 7;

    // prologue: stage X[0]
    float xf[16];
    ldx(0, xf);
    stx(0, xf);
    __syncthreads();

    // ---- hoist B (W tile) fragments into registers: constant for whole CTA ----
    uint32_t B[4][4][4];
#pragma unroll
    for (int ks = 0; ks < 4; ++ks) {
        const uint32_t uB = (uint32_t)(((ks * 2 + selB) ^ l7) * 16);
#pragma unroll
        for (int p = 0; p < 4; ++p)
            ldsm4(B[ks][p], aB0 + p * 2048 + uB);
    }

    // bias fragments
    float2 b2[8];
#pragma unroll
    for (int nf = 0; nf < 8; ++nf)
        b2[nf] = *reinterpret_cast<const float2 *>(
            smem + SM_BIAS + (wn * 64 + nf * 8 + (lane & 3) * 2) * 4);

    const float HI = 1.0f - 1e-5f;

#pragma unroll 1
    for (int t = 0; t < 8; ++t) {
        const int b = t & 1;
        if (t < 7) ldx(t + 1, xf);       // overlap gmem with mma below

        float acc[8][4];
#pragma unroll
        for (int nf = 0; nf < 8; ++nf)
#pragma unroll
            for (int c = 0; c < 4; ++c) acc[nf][c] = 0.f;

        const uint32_t aA = aA0 + (uint32_t)b * SM_XBUF;
#pragma unroll
        for (int ks = 0; ks < 4; ++ks) {
            uint32_t Ah[4];
            ldsm4(Ah, aA + (uint32_t)(((ks * 2 + selA) ^ l7) * 16));
#pragma unroll
            for (int p = 0; p < 4; ++p) {
                mma16816(acc[2 * p],     Ah, B[ks][p][0], B[ks][p][1]);
                mma16816(acc[2 * p + 1], Ah, B[ks][p][2], B[ks][p][3]);
            }
        }

        if (t < 7) stx((t + 1) & 1, xf); // fill other buffer

        // ---- epilogue: bias + clip + L1-normalize + direct store ----
        const int m0 = (grp * 8 + t) * 128;
#pragma unroll
        for (int h = 0; h < 2; ++h) {
            float v[8][2];
            float s = 0.f;
#pragma unroll
            for (int nf = 0; nf < 8; ++nf) {
                const float v0 = fminf(fmaxf(acc[nf][2 * h]     + b2[nf].x, 1e-5f), HI);
                const float v1 = fminf(fmaxf(acc[nf][2 * h + 1] + b2[nf].y, 1e-5f), HI);
                v[nf][0] = v0; v[nf][1] = v1;
                s += v0 + v1;
            }
            s += __shfl_xor_sync(0xffffffffu, s, 1);
            s += __shfl_xor_sync(0xffffffffu, s, 2);
            const float inv = __fdividef(1.0f, s);
            const int row = wm * 16 + (lane >> 2) + h * 8;
            float *op = out + (size_t)(m0 + row) * 4096 + ki0 + wn * 64 + (lane & 3) * 2;
#pragma unroll
            for (int nf = 0; nf < 8; ++nf)
                *reinterpret_cast<float2 *>(op + nf * 8) =
                    make_float2(v[nf][0] * inv, v[nf][1] * inv);
        }

        if (t < 7) __syncthreads();
    }
}

// ---------------------------------------------------------------------------
extern "C" void kernel_launch(void *const *d_in, const int *in_sizes, int n_in,
                              void *d_out, int out_size) {
    const float *x  = (const float *)d_in[0];   // (4, 64, 16384) f32
    const float *cm = (const float *)d_in[1];   // (64, 64) f32
    const float *W  = (const float *)d_in[2];   // (64, 64, 128) f32
    float *out = (float *)d_out;                // (65536, 4096) f32

    (void)in_sizes; (void)n_in; (void)out_size;

    cudaFuncSetAttribute(mma_kernel, cudaFuncAttributeMaxDynamicSharedMemorySize, SM_TOTAL);
    prep_kernel<<<64, 256>>>(W, cm);
    mma_kernel<<<dim3(32, 64), 512, SM_TOTAL>>>(x, out);
}

// round 7
// speedup vs baseline: 1.7628x; 1.7628x over previous
#include <cuda_runtime.h>
#include <cuda_fp16.h>
#include <cstdint>

#define NSEQ 16384

__device__ __half g_Wh[4096 * 64];        // [ki][j] fp16 W
__device__ float  g_bias[4096];           // [ki]
__device__ __half g_xh[4 * 64 * NSEQ];    // fp16 copy of x, same layout

// smem byte offsets
#define SM_W     0                    // [128 n][64 j] fp16 swizzled (16384)
#define SM_BIAS  16384                // 128 f32                      (512)
#define SM_X     16896                // 3 bufs x 8192: [64 j][64 m] fp16 swizzled
#define SM_XBUF  8192
#define SM_TOTAL (16896 + 3 * 8192)   // 41472

__device__ __forceinline__ uint32_t smem_u32(const void *p) {
    uint32_t a;
    asm("{ .reg .u64 t; cvta.to.shared.u64 t, %1; cvt.u32.u64 %0, t; }" : "=r"(a) : "l"(p));
    return a;
}
__device__ __forceinline__ uint32_t h2u(__half2 h) {
    return *reinterpret_cast<const uint32_t *>(&h);
}
__device__ __forceinline__ void ldsm4(uint32_t *r, uint32_t a) {
    asm volatile("ldmatrix.sync.aligned.m8n8.x4.shared.b16 {%0,%1,%2,%3}, [%4];"
                 : "=r"(r[0]), "=r"(r[1]), "=r"(r[2]), "=r"(r[3]) : "r"(a));
}
__device__ __forceinline__ void ldsm4t(uint32_t *r, uint32_t a) {
    asm volatile("ldmatrix.sync.aligned.m8n8.x4.trans.shared.b16 {%0,%1,%2,%3}, [%4];"
                 : "=r"(r[0]), "=r"(r[1]), "=r"(r[2]), "=r"(r[3]) : "r"(a));
}
__device__ __forceinline__ void mma16816(float *c, const uint32_t *a, uint32_t b0, uint32_t b1) {
    asm volatile("mma.sync.aligned.m16n8k16.row.col.f32.f16.f16.f32 "
                 "{%0,%1,%2,%3}, {%4,%5,%6,%7}, {%8,%9}, {%0,%1,%2,%3};"
                 : "+f"(c[0]), "+f"(c[1]), "+f"(c[2]), "+f"(c[3])
                 : "r"(a[0]), "r"(a[1]), "r"(a[2]), "r"(a[3]), "r"(b0), "r"(b1));
}
__device__ __forceinline__ void cpa16(uint32_t dst, const void *src) {
    asm volatile("cp.async.cg.shared.global [%0], [%1], 16;" :: "r"(dst), "l"(src));
}
__device__ __forceinline__ void cpa_commit() {
    asm volatile("cp.async.commit_group;" ::: "memory");
}
template <int N> __device__ __forceinline__ void cpa_wait() {
    asm volatile("cp.async.wait_group %0;" :: "n"(N) : "memory");
}

// ---------------------------------------------------------------------------
// Prep A: W -> fp16 g_Wh [ki][j]; bias[ki] = cm[k] . Wcm[k][i]
// ---------------------------------------------------------------------------
__global__ void prep_kernel(const float *__restrict__ W, const float *__restrict__ cm) {
    const int k = blockIdx.x, tid = threadIdx.x;
    const float *Wk = W + k * 64 * 128;
#pragma unroll
    for (int t = 0; t < 16; ++t) {
        int e = tid + t * 256;
        int i = e >> 6, j = e & 63;
        g_Wh[(k * 64 + i) * 64 + j] = __float2half_rn(Wk[i * 128 + j]);
    }
    if (tid < 64) {
        const int i = tid;
        const float *cmk = cm + k * 64;
        float s = 0.f;
#pragma unroll 8
        for (int j = 0; j < 64; ++j)
            s = fmaf(cmk[j], Wk[i * 128 + 64 + j], s);
        g_bias[k * 64 + i] = s;
    }
}

// ---------------------------------------------------------------------------
// Prep B: x f32 -> fp16 g_xh (same layout). 1024 x 256, 16 elems/thread.
// ---------------------------------------------------------------------------
__global__ void prepx_kernel(const float *__restrict__ x) {
    const int t = blockIdx.x * 256 + threadIdx.x;
    const float4 *src = reinterpret_cast<const float4 *>(x) + (size_t)t * 4;
    uint4 *dst = reinterpret_cast<uint4 *>(g_xh) + (size_t)t * 2;
#pragma unroll
    for (int h = 0; h < 2; ++h) {
        float4 a = src[2 * h], b = src[2 * h + 1];
        uint32_t p0 = h2u(__float22half2_rn(make_float2(a.x, a.y)));
        uint32_t p1 = h2u(__float22half2_rn(make_float2(a.z, a.w)));
        uint32_t p2 = h2u(__float22half2_rn(make_float2(b.x, b.y)));
        uint32_t p3 = h2u(__float22half2_rn(make_float2(b.z, b.w)));
        dst[h] = make_uint4(p0, p1, p2, p3);
    }
}

// ---------------------------------------------------------------------------
// Main: 256 threads (8 warps = 4m x 2n), CTA tile 64m x 128ki, K=64.
// 16 m-tiles per CTA. X staged [64 j][64 m] fp16 via cp.async (3-stage),
// A frags via ldmatrix.trans. B (W) hoisted to regs once. 2 CTAs/SM.
// ---------------------------------------------------------------------------
__global__ __launch_bounds__(256, 2)
void mma_kernel(float *__restrict__ out) {
    extern __shared__ char smem[];
    const uint32_t sb = smem_u32(smem);
    const int tid = threadIdx.x;
    const int lane = tid & 31, wid = tid >> 5;
    const int wm = wid & 3, wn = wid >> 2;
    const int ki0 = blockIdx.x * 128;
    const int grp = blockIdx.y;          // 0..63, 16 m-tiles of 64 each

    // ---- per-thread staging constants: 2 chunks (tid, tid+256) ----
    const int cj0 = tid >> 3, cp0 = tid & 7;           // chunk 0: j, part
    const int cj1 = (tid + 256) >> 3, cp1 = tid & 7;   // chunk 1
    const uint32_t d0 = sb + SM_X + (uint32_t)cj0 * 128 + (uint32_t)((cp0 ^ (cj0 & 7)) * 16);
    const uint32_t d1 = sb + SM_X + (uint32_t)cj1 * 128 + (uint32_t)((cp1 ^ (cj1 & 7)) * 16);

    auto stage_x = [&](int t, int buf) {
        const int m0 = (grp * 16 + t) * 64;
        const __half *xb = g_xh + ((size_t)(m0 >> 14) * 64) * NSEQ + (m0 & (NSEQ - 1));
        cpa16(d0 + (uint32_t)buf * SM_XBUF, xb + (size_t)cj0 * NSEQ + cp0 * 8);
        cpa16(d1 + (uint32_t)buf * SM_XBUF, xb + (size_t)cj1 * NSEQ + cp1 * 8);
        cpa_commit();
    };

    // prologue: start tiles 0,1
    stage_x(0, 0);
    stage_x(1, 1);

    // ---- stage W (swizzled, once) + bias ----
    {
#pragma unroll
        for (int q = 0; q < 4; ++q) {
            const int c = tid + q * 256;          // 1024 chunks
            const int n = c >> 3, ch = c & 7;
            const uint4 w = *reinterpret_cast<const uint4 *>(g_Wh + (ki0 + n) * 64 + ch * 8);
            *reinterpret_cast<uint4 *>(smem + SM_W + n * 128 + ((ch ^ (n & 7)) * 16)) = w;
        }
        if (tid < 128) reinterpret_cast<float *>(smem + SM_BIAS)[tid] = g_bias[ki0 + tid];
    }

    cpa_wait<1>();        // tile 0 resident
    __syncthreads();

    // ---- hoist B (W tile) fragments: constant for whole CTA ----
    const int l7 = lane & 7;
    const int rBl = (lane & 7) + ((lane >> 4) << 3);
    const uint32_t aB0 = sb + SM_W + (uint32_t)(wn * 64 + rBl) * 128;
    const int selB = (lane >> 3) & 1;
    uint32_t B[4][4][4];
#pragma unroll
    for (int ks = 0; ks < 4; ++ks) {
        const uint32_t uB = (uint32_t)(((ks * 2 + selB) ^ l7) * 16);
#pragma unroll
        for (int p = 0; p < 4; ++p)
            ldsm4(B[ks][p], aB0 + p * 2048 + uB);
    }

    // A-frag (trans) lane constants: j-row and m-chunk
    const int jjl = (lane & 7) + ((lane >> 4) & 1) * 8;          // j within 16-block
    const int mcA = wm * 2 + ((lane >> 3) & 1);                  // m-chunk (8m)
    const uint32_t aA0 = sb + SM_X + (uint32_t)jjl * 128 + (uint32_t)((mcA ^ l7) * 16);

    const float *bsp = reinterpret_cast<const float *>(smem + SM_BIAS) + wn * 64 + (lane & 3) * 2;
    const float HI = 1.0f - 1e-5f;

    int buf = 0;
#pragma unroll 1
    for (int t = 0; t < 16; ++t) {
        if (t + 2 < 16) {
            int b2i = buf + 2; if (b2i >= 3) b2i -= 3;
            stage_x(t + 2, b2i);
        }

        float acc[8][4];
#pragma unroll
        for (int nf = 0; nf < 8; ++nf)
#pragma unroll
            for (int c = 0; c < 4; ++c) acc[nf][c] = 0.f;

        const uint32_t aA = aA0 + (uint32_t)buf * SM_XBUF;
#pragma unroll
        for (int ks = 0; ks < 4; ++ks) {
            uint32_t Af[4];
            ldsm4t(Af, aA + (uint32_t)ks * 2048);
#pragma unroll
            for (int p = 0; p < 4; ++p) {
                mma16816(acc[2 * p],     Af, B[ks][p][0], B[ks][p][1]);
                mma16816(acc[2 * p + 1], Af, B[ks][p][2], B[ks][p][3]);
            }
        }

        // ---- epilogue: bias + clip + L1-normalize + direct STG.64 ----
        const int m0 = (grp * 16 + t) * 64;
#pragma unroll
        for (int h = 0; h < 2; ++h) {
            float v[8][2];
            float s = 0.f;
#pragma unroll
            for (int nf = 0; nf < 8; ++nf) {
                const float2 bb = *reinterpret_cast<const float2 *>(bsp + nf * 8);
                const float v0 = fminf(fmaxf(acc[nf][2 * h]     + bb.x, 1e-5f), HI);
                const float v1 = fminf(fmaxf(acc[nf][2 * h + 1] + bb.y, 1e-5f), HI);
                v[nf][0] = v0; v[nf][1] = v1;
                s += v0 + v1;
            }
            s += __shfl_xor_sync(0xffffffffu, s, 1);
            s += __shfl_xor_sync(0xffffffffu, s, 2);
            const float inv = __fdividef(1.0f, s);
            const int row = wm * 16 + (lane >> 2) + h * 8;
            float *op = out + (size_t)(m0 + row) * 4096 + ki0 + wn * 64 + (lane & 3) * 2;
#pragma unroll
            for (int nf = 0; nf < 8; ++nf)
                *reinterpret_cast<float2 *>(op + nf * 8) =
                    make_float2(v[nf][0] * inv, v[nf][1] * inv);
        }

        if (t + 2 < 16) cpa_wait<1>();   // tile t+1 resident (t+2 may be in flight)
        else            cpa_wait<0>();
        if (t < 15) __syncthreads();

        if (++buf == 3) buf = 0;
    }
}

// ---------------------------------------------------------------------------
extern "C" void kernel_launch(void *const *d_in, const int *in_sizes, int n_in,
                              void *d_out, int out_size) {
    const float *x  = (const float *)d_in[0];   // (4, 64, 16384) f32
    const float *cm = (const float *)d_in[1];   // (64, 64) f32
    const float *W  = (const float *)d_in[2];   // (64, 64, 128) f32
    float *out = (float *)d_out;                // (65536, 4096) f32

    (void)in_sizes; (void)n_in; (void)out_size;

    cudaFuncSetAttribute(mma_kernel, cudaFuncAttributeMaxDynamicSharedMemorySize, SM_TOTAL);
    prep_kernel<<<64, 256>>>(W, cm);
    prepx_kernel<<<1024, 256>>>(x);
    mma_kernel<<<dim3(32, 64), 256, SM_TOTAL>>>(out);
}